// round 1
// baseline (speedup 1.0000x reference)
#include <cuda_runtime.h>

#define B_   8
#define TGT  256
#define SRC  256
#define DM   512
#define TT   32
#define LPAD 260   // 256 + 4 pad: breaks stride-256 bank collision, keeps 16B alignment

// scratch (no allocation allowed -> __device__ globals)
__device__ float g_dt[B_ * TGT * SRC];   // dec @ W1  [B,T,L]
__device__ float g_et[B_ * SRC * SRC];   // enc @ W2  [B,S,L]
__device__ float g_sc[B_ * TGT * SRC];   // scores    [B,T,S]

__device__ __forceinline__ float tanha(float x) {
    float y;
    asm("tanh.approx.f32 %0, %1;" : "=f"(y) : "f"(x));
    return y;
}

// ---------------------------------------------------------------------------
// C[M=2048][256] = A[2048][512] @ W[512][256], fp32 smem-tiled, 64x64 tile
// ---------------------------------------------------------------------------
__global__ __launch_bounds__(256) void gemm_kernel(const float* __restrict__ A,
                                                   const float* __restrict__ W,
                                                   int which) {
    __shared__ float As[16][68];  // transposed A tile: As[k][m]
    __shared__ float Bs[16][68];
    float* C = which ? g_et : g_dt;
    int tid = threadIdx.x;
    int bm = blockIdx.x * 64, bn = blockIdx.y * 64;
    int tm = (tid & 15) * 4, tn = (tid >> 4) * 4;
    int arow = tid >> 2, acol = (tid & 3) * 4;
    int brow = tid >> 4, bcol = (tid & 15) * 4;
    float acc[4][4] = {};
    for (int k0 = 0; k0 < DM; k0 += 16) {
        float4 va = *(const float4*)&A[(bm + arow) * DM + k0 + acol];
        As[acol + 0][arow] = va.x;
        As[acol + 1][arow] = va.y;
        As[acol + 2][arow] = va.z;
        As[acol + 3][arow] = va.w;
        *(float4*)&Bs[brow][bcol] = *(const float4*)&W[(k0 + brow) * SRC + bn + bcol];
        __syncthreads();
#pragma unroll
        for (int k = 0; k < 16; k++) {
            float4 av = *(const float4*)&As[k][tm];
            float4 bv = *(const float4*)&Bs[k][tn];
            float a_[4] = {av.x, av.y, av.z, av.w};
            float b_[4] = {bv.x, bv.y, bv.z, bv.w};
#pragma unroll
            for (int i = 0; i < 4; i++)
#pragma unroll
                for (int j = 0; j < 4; j++) acc[i][j] = fmaf(a_[i], b_[j], acc[i][j]);
        }
        __syncthreads();
    }
#pragma unroll
    for (int i = 0; i < 4; i++)
        *(float4*)&C[(bm + tm + i) * SRC + bn + tn] =
            make_float4(acc[i][0], acc[i][1], acc[i][2], acc[i][3]);
}

// ---------------------------------------------------------------------------
// scores[b,t,s] = sum_l vt[l] * tanh(dt[b,t,l] + et[b,s,l])
// block = 256 threads, tile 32t x 32s, each thread a 2x2 (t,s) micro-tile
// ---------------------------------------------------------------------------
__global__ __launch_bounds__(256) void scores_kernel(const float* __restrict__ vt) {
    extern __shared__ float sm[];
    float* sdt = sm;                  // [TT][LPAD]
    float* set = sm + TT * LPAD;      // [TT][LPAD]
    float* svt = sm + 2 * TT * LPAD;  // [256]
    int tid = threadIdx.x;
    int b = blockIdx.z, t0 = blockIdx.y * TT, s0 = blockIdx.x * TT;
    const float* dtp = g_dt + (b * TGT + t0) * SRC;
    const float* etp = g_et + (b * SRC + s0) * SRC;
#pragma unroll
    for (int i = 0; i < 8; i++) {
        int idx = tid + i * 256;           // 2048 float4s total
        int r = idx >> 6, c = (idx & 63) * 4;
        *(float4*)&sdt[r * LPAD + c] = *(const float4*)&dtp[r * SRC + c];
        *(float4*)&set[r * LPAD + c] = *(const float4*)&etp[r * SRC + c];
    }
    if (tid < 64) *(float4*)&svt[tid * 4] = *(const float4*)&vt[tid * 4];
    __syncthreads();

    int tx = tid & 15, ty = tid >> 4;
    const float* dA = &sdt[ty * LPAD];
    const float* dB = &sdt[(ty + 16) * LPAD];
    const float* eA = &set[tx * LPAD];
    const float* eB = &set[(tx + 16) * LPAD];
    float a00 = 0.f, a01 = 0.f, a10 = 0.f, a11 = 0.f;
#pragma unroll 8
    for (int c = 0; c < 64; c++) {
        float4 v  = *(const float4*)&svt[c * 4];
        float4 x0 = *(const float4*)&dA[c * 4];
        float4 x1 = *(const float4*)&dB[c * 4];
        float4 y0 = *(const float4*)&eA[c * 4];
        float4 y1 = *(const float4*)&eB[c * 4];
#define STEP(f)                                   \
    {                                             \
        a00 = fmaf(v.f, tanha(x0.f + y0.f), a00); \
        a01 = fmaf(v.f, tanha(x0.f + y1.f), a01); \
        a10 = fmaf(v.f, tanha(x1.f + y0.f), a10); \
        a11 = fmaf(v.f, tanha(x1.f + y1.f), a11); \
    }
        STEP(x) STEP(y) STEP(z) STEP(w)
#undef STEP
    }
    float* sc = g_sc + (b * TGT + t0) * SRC + s0;
    sc[ty * SRC + tx] = a00;
    sc[ty * SRC + tx + 16] = a01;
    sc[(ty + 16) * SRC + tx] = a10;
    sc[(ty + 16) * SRC + tx + 16] = a11;
}

// ---------------------------------------------------------------------------
// masked log_softmax over s + transpose to out[b, s, t]
// one block per (b, t) row of 256
// ---------------------------------------------------------------------------
__global__ __launch_bounds__(256) void softmax_kernel(const int* __restrict__ lens,
                                                      float* __restrict__ out) {
    __shared__ float red[8];
    int bt = blockIdx.x;
    int b = bt >> 8, t = bt & 255;
    int s = threadIdx.x;
    float x = g_sc[bt * 256 + s];
    if (s >= lens[b]) x += logf(1e-8f);  // log(mask + eps); valid lanes: log(1.0f)=0
    float m = x;
#pragma unroll
    for (int o = 16; o; o >>= 1) m = fmaxf(m, __shfl_xor_sync(0xffffffffu, m, o));
    if ((s & 31) == 0) red[s >> 5] = m;
    __syncthreads();
    m = red[0];
#pragma unroll
    for (int i = 1; i < 8; i++) m = fmaxf(m, red[i]);
    float e = __expf(x - m);
    float sum = e;
#pragma unroll
    for (int o = 16; o; o >>= 1) sum += __shfl_xor_sync(0xffffffffu, sum, o);
    __syncthreads();
    if ((s & 31) == 0) red[s >> 5] = sum;
    __syncthreads();
    sum = 0.f;
#pragma unroll
    for (int i = 0; i < 8; i++) sum += red[i];
    float lse = m + logf(sum);
    out[(b * 256 + s) * 256 + t] = x - lse;
}

extern "C" void kernel_launch(void* const* d_in, const int* in_sizes, int n_in,
                              void* d_out, int out_size) {
    const float* dec  = (const float*)d_in[0];
    const float* enc  = (const float*)d_in[1];
    const int*   lens = (const int*)d_in[2];
    const float* W1   = (const float*)d_in[3];
    const float* W2   = (const float*)d_in[4];
    const float* vt   = (const float*)d_in[5];
    float*       out  = (float*)d_out;

    gemm_kernel<<<dim3(32, 4), 256>>>(dec, W1, 0);
    gemm_kernel<<<dim3(32, 4), 256>>>(enc, W2, 1);

    constexpr int SMEM = (2 * TT * LPAD + 256) * sizeof(float);
    cudaFuncSetAttribute(scores_kernel, cudaFuncAttributeMaxDynamicSharedMemorySize, SMEM);
    scores_kernel<<<dim3(SRC / TT, TGT / TT, B_), 256, SMEM>>>(vt);

    softmax_kernel<<<B_ * TGT, 256>>>(lens, out);
}

// round 2
// speedup vs baseline: 1.0639x; 1.0639x over previous
#include <cuda_runtime.h>
#include <cuda_fp16.h>

#define B_   8
#define TGT  256
#define SRC  256
#define DM   512
#define PITCH 132           // half2 words per smem row (128 + 4 pad; 132 mod 32 = 4)
#define LOGEPS (-18.420680743952367f)

// scratch (no allocation allowed -> __device__ globals)
__device__ unsigned g_dt[B_ * TGT * (SRC / 2)];  // dec @ W1  [B,T,L] as half2
__device__ unsigned g_et[B_ * SRC * (SRC / 2)];  // enc @ W2  [B,S,L] as half2
__device__ float    g_sc[B_ * TGT * SRC];        // scores    [B,T,S] fp32

__device__ __forceinline__ __half2 tanh2(__half2 x) {
    unsigned xi = *(unsigned*)&x, yi;
    asm("tanh.approx.f16x2 %0, %1;" : "=r"(yi) : "r"(xi));
    return *(__half2*)&yi;
}
__device__ __forceinline__ __half2 uh(unsigned u) { return *(__half2*)&u; }
__device__ __forceinline__ float h2sum(__half2 h) {
    float2 f = __half22float2(h);
    return f.x + f.y;
}

// ---------------------------------------------------------------------------
// Both GEMMs in one launch. z=0: g_dt = dec@W1 ; z=1: g_et = enc@W2
// C[2048][256] = A[2048][512] @ W[512][256], 32x64 tiles, f16x2 output
// ---------------------------------------------------------------------------
__global__ __launch_bounds__(256) void gemm_kernel(const float* __restrict__ dec,
                                                   const float* __restrict__ enc,
                                                   const float* __restrict__ W1,
                                                   const float* __restrict__ W2) {
    __shared__ float As[16][33];  // transposed: As[k][m]
    __shared__ float Bs[16][68];
    int z = blockIdx.z;
    const float* A = z ? enc : dec;
    const float* W = z ? W2 : W1;
    unsigned* C = z ? g_et : g_dt;
    int tid = threadIdx.x;
    int bm = blockIdx.x * 32, bn = blockIdx.y * 64;
    int tm = (tid & 15) * 2, tn = (tid >> 4) * 4;
    float acc[2][4] = {};
    for (int k0 = 0; k0 < DM; k0 += 16) {
        if (tid < 128) {
            int r = tid >> 2, kc = (tid & 3) * 4;
            float4 va = *(const float4*)&A[(bm + r) * DM + k0 + kc];
            As[kc + 0][r] = va.x;
            As[kc + 1][r] = va.y;
            As[kc + 2][r] = va.z;
            As[kc + 3][r] = va.w;
        }
        {
            int kr = tid >> 4, nc = (tid & 15) * 4;
            *(float4*)&Bs[kr][nc] = *(const float4*)&W[(k0 + kr) * SRC + bn + nc];
        }
        __syncthreads();
#pragma unroll
        for (int k = 0; k < 16; k++) {
            float a0 = As[k][tm], a1 = As[k][tm + 1];
            float4 b = *(const float4*)&Bs[k][tn];
            acc[0][0] = fmaf(a0, b.x, acc[0][0]);
            acc[0][1] = fmaf(a0, b.y, acc[0][1]);
            acc[0][2] = fmaf(a0, b.z, acc[0][2]);
            acc[0][3] = fmaf(a0, b.w, acc[0][3]);
            acc[1][0] = fmaf(a1, b.x, acc[1][0]);
            acc[1][1] = fmaf(a1, b.y, acc[1][1]);
            acc[1][2] = fmaf(a1, b.z, acc[1][2]);
            acc[1][3] = fmaf(a1, b.w, acc[1][3]);
        }
        __syncthreads();
    }
#pragma unroll
    for (int i = 0; i < 2; i++) {
        __half2 h0 = __floats2half2_rn(acc[i][0], acc[i][1]);
        __half2 h1 = __floats2half2_rn(acc[i][2], acc[i][3]);
        uint2 st = make_uint2(*(unsigned*)&h0, *(unsigned*)&h1);
        *(uint2*)&C[(bm + tm + i) * (SRC / 2) + (bn + tn) / 2] = st;
    }
}

// ---------------------------------------------------------------------------
// scores[b,t,s] = sum_l vt[l] * tanh(dt[b,t,l] + et[b,s,l]), all f16x2 math,
// HFMA2 accumulate with fp32 flush every 64 l. 32x32 tile, 2x2 micro-tile.
// ---------------------------------------------------------------------------
__global__ __launch_bounds__(256) void scores_kernel(const float* __restrict__ vt) {
    __shared__ unsigned sdt[32 * PITCH];
    __shared__ unsigned set[32 * PITCH];
    __shared__ unsigned svt[128];
    int tid = threadIdx.x;
    int b = blockIdx.z, t0 = blockIdx.y * 32, s0 = blockIdx.x * 32;
    const unsigned* dtp = g_dt + (b * TGT + t0) * (SRC / 2);
    const unsigned* etp = g_et + (b * SRC + s0) * (SRC / 2);
#pragma unroll
    for (int i = 0; i < 4; i++) {
        int idx = tid + i * 256;  // 1024 uint4 per tile
        int r = idx >> 5, q = (idx & 31) * 4;
        *(uint4*)&sdt[r * PITCH + q] = *(const uint4*)&dtp[r * (SRC / 2) + q];
        *(uint4*)&set[r * PITCH + q] = *(const uint4*)&etp[r * (SRC / 2) + q];
    }
    if (tid < 128) {
        __half2 h = __floats2half2_rn(vt[2 * tid], vt[2 * tid + 1]);
        svt[tid] = *(unsigned*)&h;
    }
    __syncthreads();

    int tx = tid & 15, ty = tid >> 4;
    const uint4* pv = (const uint4*)svt;
    const uint4* dA = (const uint4*)(sdt + ty * PITCH);
    const uint4* dB = (const uint4*)(sdt + (ty + 16) * PITCH);
    const uint4* eA = (const uint4*)(set + tx * PITCH);
    const uint4* eB = (const uint4*)(set + (tx + 16) * PITCH);
    float a00 = 0.f, a01 = 0.f, a10 = 0.f, a11 = 0.f;
    for (int p = 0; p < 4; p++) {  // 4 phases x 8 chunks x 4 half2 = 256 l
        __half2 s00 = __float2half2_rn(0.f), s01 = s00, s10 = s00, s11 = s00;
#pragma unroll
        for (int c = p * 8; c < p * 8 + 8; c++) {
            uint4 vv = pv[c];
            uint4 x0 = dA[c], x1 = dB[c];
            uint4 y0 = eA[c], y1 = eB[c];
#define STEP(U)                                                 \
    {                                                           \
        __half2 v = uh(vv.U);                                   \
        __half2 xa = uh(x0.U), xb = uh(x1.U);                   \
        __half2 ya = uh(y0.U), yb = uh(y1.U);                   \
        s00 = __hfma2(tanh2(__hadd2(xa, ya)), v, s00);          \
        s01 = __hfma2(tanh2(__hadd2(xa, yb)), v, s01);          \
        s10 = __hfma2(tanh2(__hadd2(xb, ya)), v, s10);          \
        s11 = __hfma2(tanh2(__hadd2(xb, yb)), v, s11);          \
    }
            STEP(x) STEP(y) STEP(z) STEP(w)
#undef STEP
        }
        a00 += h2sum(s00);
        a01 += h2sum(s01);
        a10 += h2sum(s10);
        a11 += h2sum(s11);
    }
    float* sc = g_sc + (b * TGT + t0) * SRC + s0;
    sc[ty * SRC + tx] = a00;
    sc[ty * SRC + tx + 16] = a01;
    sc[(ty + 16) * SRC + tx] = a10;
    sc[(ty + 16) * SRC + tx + 16] = a11;
}

// ---------------------------------------------------------------------------
// masked log_softmax over s + transpose to out[b,s,t], coalesced stores.
// grid (8 t-tiles, 8 b), block 256. 32 t-rows per block staged in smem.
// ---------------------------------------------------------------------------
__global__ __launch_bounds__(256) void softmax_kernel(const int* __restrict__ lens,
                                                      float* __restrict__ out) {
    __shared__ float sm[32][257];
    __shared__ float slse[32];
    int tid = threadIdx.x;
    int t0 = blockIdx.x * 32, b = blockIdx.y;
    int len = lens[b];
    const float* scp = g_sc + (b * TGT + t0) * SRC;
#pragma unroll
    for (int i = 0; i < 32; i++) {
        int idx = tid + i * 256;
        int r = idx >> 8, s = idx & 255;
        float v = scp[r * SRC + s];
        if (s >= len) v += LOGEPS;
        sm[r][s] = v;
    }
    __syncthreads();
    int w = tid >> 5, lane = tid & 31;
#pragma unroll
    for (int rr = 0; rr < 4; rr++) {
        int row = w * 4 + rr;
        float m = -1e30f;
        float x[8];
#pragma unroll
        for (int j = 0; j < 8; j++) {
            x[j] = sm[row][lane + 32 * j];
            m = fmaxf(m, x[j]);
        }
#pragma unroll
        for (int o = 16; o; o >>= 1) m = fmaxf(m, __shfl_xor_sync(0xffffffffu, m, o));
        float sum = 0.f;
#pragma unroll
        for (int j = 0; j < 8; j++) sum += __expf(x[j] - m);
#pragma unroll
        for (int o = 16; o; o >>= 1) sum += __shfl_xor_sync(0xffffffffu, sum, o);
        if (lane == 0) slse[row] = m + logf(sum);
    }
    __syncthreads();
    float* op = out + b * SRC * TGT;  // out[b][s][t]
#pragma unroll
    for (int i = 0; i < 32; i++) {
        int idx = tid + i * 256;
        int t = idx & 31, s = idx >> 5;
        op[s * TGT + t0 + t] = sm[t][s] - slse[t];
    }
}

extern "C" void kernel_launch(void* const* d_in, const int* in_sizes, int n_in,
                              void* d_out, int out_size) {
    const float* dec  = (const float*)d_in[0];
    const float* enc  = (const float*)d_in[1];
    const int*   lens = (const int*)d_in[2];
    const float* W1   = (const float*)d_in[3];
    const float* W2   = (const float*)d_in[4];
    const float* vt   = (const float*)d_in[5];
    float*       out  = (float*)d_out;

    gemm_kernel<<<dim3(64, 4, 2), 256>>>(dec, enc, W1, W2);
    scores_kernel<<<dim3(8, 8, 8), 256>>>(vt);
    softmax_kernel<<<dim3(8, 8), 256>>>(lens, out);
}

// round 3
// speedup vs baseline: 1.6217x; 1.5242x over previous
#include <cuda_runtime.h>
#include <cuda_fp16.h>

#define B_   8
#define TGT  256
#define SRC  256
#define DM   512
#define PITCH 132           // half2 words per smem row (128 + 4 pad)
#define LOGEPS (-18.420680743952367f)

// scratch (no allocation allowed -> __device__ globals)
__device__ unsigned g_dt[B_ * TGT * (SRC / 2)];  // dec @ W1  [B,T,L] as half2
__device__ unsigned g_et[B_ * SRC * (SRC / 2)];  // enc @ W2  [B,S,L] as half2
__device__ float    g_sc[B_ * TGT * SRC];        // scores    [B,T,S] fp32

__device__ __forceinline__ __half2 tanh2(__half2 x) {
    unsigned xi = *(unsigned*)&x, yi;
    asm("tanh.approx.f16x2 %0, %1;" : "=r"(yi) : "r"(xi));
    return *(__half2*)&yi;
}
__device__ __forceinline__ __half2 uh(unsigned u) { return *(__half2*)&u; }
__device__ __forceinline__ float h2sum(__half2 h) {
    float2 f = __half22float2(h);
    return f.x + f.y;
}

__device__ __forceinline__ void ldsm4(unsigned& r0, unsigned& r1, unsigned& r2,
                                      unsigned& r3, unsigned addr) {
    asm volatile("ldmatrix.sync.aligned.m8n8.x4.shared.b16 {%0,%1,%2,%3}, [%4];"
                 : "=r"(r0), "=r"(r1), "=r"(r2), "=r"(r3) : "r"(addr));
}
__device__ __forceinline__ void ldsm4t(unsigned& r0, unsigned& r1, unsigned& r2,
                                       unsigned& r3, unsigned addr) {
    asm volatile("ldmatrix.sync.aligned.m8n8.x4.trans.shared.b16 {%0,%1,%2,%3}, [%4];"
                 : "=r"(r0), "=r"(r1), "=r"(r2), "=r"(r3) : "r"(addr));
}
__device__ __forceinline__ void mma16816(float* c, const unsigned* a, unsigned b0,
                                         unsigned b1) {
    asm volatile(
        "mma.sync.aligned.m16n8k16.row.col.f32.f16.f16.f32 "
        "{%0,%1,%2,%3}, {%4,%5,%6,%7}, {%8,%9}, {%0,%1,%2,%3};"
        : "+f"(c[0]), "+f"(c[1]), "+f"(c[2]), "+f"(c[3])
        : "r"(a[0]), "r"(a[1]), "r"(a[2]), "r"(a[3]), "r"(b0), "r"(b1));
}

// ---------------------------------------------------------------------------
// Tensor-core GEMM. z=0: g_dt = dec@W1 ; z=1: g_et = enc@W2
// C[2048][256] = A[2048][512] @ W[512][256], fp16 in / fp32 accum / fp16 out.
// Block: 128 threads (4 warps), tile 64x64, BK=32. Warp w: rows [16w,16w+16).
// ---------------------------------------------------------------------------
#define APITCH 40  // halves; 80B rows -> conflict-free ldmatrix
#define BPITCH 72  // halves; 144B rows -> conflict-free ldmatrix.trans
__global__ __launch_bounds__(128) void gemm_kernel(const float* __restrict__ dec,
                                                   const float* __restrict__ enc,
                                                   const float* __restrict__ W1,
                                                   const float* __restrict__ W2) {
    __shared__ __half As[64 * APITCH];
    __shared__ __half Bs[32 * BPITCH];
    int z = blockIdx.z;
    const float* A = z ? enc : dec;
    const float* W = z ? W2 : W1;
    unsigned* C = z ? g_et : g_dt;
    int tid = threadIdx.x;
    int warp = tid >> 5, lane = tid & 31;
    int bm = blockIdx.x * 64, bn = blockIdx.y * 64;

    unsigned As_base = (unsigned)__cvta_generic_to_shared(As);
    unsigned Bs_base = (unsigned)__cvta_generic_to_shared(Bs);
    // ldmatrix source addresses (halves -> *2 bytes)
    int lm_r = lane & 15, lm_c = (lane >> 4) * 8;
    unsigned a_addr = As_base + ((warp * 16 + lm_r) * APITCH + lm_c) * 2;
    unsigned b_addr = Bs_base + (lm_r * BPITCH + lm_c) * 2;

    float acc[8][4] = {};
    for (int k0 = 0; k0 < DM; k0 += 32) {
        // stage A tile 64x32 (fp32->fp16)
#pragma unroll
        for (int i = 0; i < 4; i++) {
            int idx = tid + i * 128;            // 512 float4
            int r = idx >> 3, q = (idx & 7) * 4;
            float4 v = *(const float4*)&A[(bm + r) * DM + k0 + q];
            __half2 h0 = __floats2half2_rn(v.x, v.y);
            __half2 h1 = __floats2half2_rn(v.z, v.w);
            *(uint2*)&As[r * APITCH + q] = make_uint2(*(unsigned*)&h0, *(unsigned*)&h1);
        }
        // stage B tile 32x64 (fp32->fp16)
#pragma unroll
        for (int i = 0; i < 4; i++) {
            int idx = tid + i * 128;            // 512 float4
            int kr = idx >> 4, q = (idx & 15) * 4;
            float4 v = *(const float4*)&W[(k0 + kr) * SRC + bn + q];
            __half2 h0 = __floats2half2_rn(v.x, v.y);
            __half2 h1 = __floats2half2_rn(v.z, v.w);
            *(uint2*)&Bs[kr * BPITCH + q] = make_uint2(*(unsigned*)&h0, *(unsigned*)&h1);
        }
        __syncthreads();
#pragma unroll
        for (int ks = 0; ks < 32; ks += 16) {
            unsigned a[4];
            ldsm4(a[0], a[1], a[2], a[3], a_addr + ks * 2);
#pragma unroll
            for (int nt = 0; nt < 4; nt++) {
                unsigned b[4];
                ldsm4t(b[0], b[1], b[2], b[3], b_addr + (ks * BPITCH + nt * 16) * 2);
                mma16816(acc[2 * nt], a, b[0], b[1]);
                mma16816(acc[2 * nt + 1], a, b[2], b[3]);
            }
        }
        __syncthreads();
    }
    // epilogue: fp32 -> half2 stores
    int r0 = bm + warp * 16 + (lane >> 2);
    int cp = (lane & 3);  // half2 column pair within 8-wide n-tile
#pragma unroll
    for (int j = 0; j < 8; j++) {
        int colpair = (bn + j * 8) / 2 + cp;
        __half2 h01 = __floats2half2_rn(acc[j][0], acc[j][1]);
        __half2 h23 = __floats2half2_rn(acc[j][2], acc[j][3]);
        C[r0 * (SRC / 2) + colpair] = *(unsigned*)&h01;
        C[(r0 + 8) * (SRC / 2) + colpair] = *(unsigned*)&h23;
    }
}

// ---------------------------------------------------------------------------
// scores[b,t,s] = sum_l vt[l] * tanh(dt[b,t,l] + et[b,s,l]), f16x2 math,
// HFMA2 accumulate with fp32 flush every 64 l. 32x32 tile, 2x2 micro-tile.
// ---------------------------------------------------------------------------
__global__ __launch_bounds__(256) void scores_kernel(const float* __restrict__ vt) {
    __shared__ unsigned sdt[32 * PITCH];
    __shared__ unsigned set[32 * PITCH];
    __shared__ unsigned svt[128];
    int tid = threadIdx.x;
    int b = blockIdx.z, t0 = blockIdx.y * 32, s0 = blockIdx.x * 32;
    const unsigned* dtp = g_dt + (b * TGT + t0) * (SRC / 2);
    const unsigned* etp = g_et + (b * SRC + s0) * (SRC / 2);
#pragma unroll
    for (int i = 0; i < 4; i++) {
        int idx = tid + i * 256;  // 1024 uint4 per tile
        int r = idx >> 5, q = (idx & 31) * 4;
        *(uint4*)&sdt[r * PITCH + q] = *(const uint4*)&dtp[r * (SRC / 2) + q];
        *(uint4*)&set[r * PITCH + q] = *(const uint4*)&etp[r * (SRC / 2) + q];
    }
    if (tid < 128) {
        __half2 h = __floats2half2_rn(vt[2 * tid], vt[2 * tid + 1]);
        svt[tid] = *(unsigned*)&h;
    }
    __syncthreads();

    int tx = tid & 15, ty = tid >> 4;
    const uint4* pv = (const uint4*)svt;
    const uint4* dA = (const uint4*)(sdt + ty * PITCH);
    const uint4* dB = (const uint4*)(sdt + (ty + 16) * PITCH);
    const uint4* eA = (const uint4*)(set + tx * PITCH);
    const uint4* eB = (const uint4*)(set + (tx + 16) * PITCH);
    float a00 = 0.f, a01 = 0.f, a10 = 0.f, a11 = 0.f;
    for (int p = 0; p < 4; p++) {  // 4 phases x 8 chunks x 4 half2 = 256 l
        __half2 s00 = __float2half2_rn(0.f), s01 = s00, s10 = s00, s11 = s00;
#pragma unroll
        for (int c = p * 8; c < p * 8 + 8; c++) {
            uint4 vv = pv[c];
            uint4 x0 = dA[c], x1 = dB[c];
            uint4 y0 = eA[c], y1 = eB[c];
#define STEP(U)                                                 \
    {                                                           \
        __half2 v = uh(vv.U);                                   \
        __half2 xa = uh(x0.U), xb = uh(x1.U);                   \
        __half2 ya = uh(y0.U), yb = uh(y1.U);                   \
        s00 = __hfma2(tanh2(__hadd2(xa, ya)), v, s00);          \
        s01 = __hfma2(tanh2(__hadd2(xa, yb)), v, s01);          \
        s10 = __hfma2(tanh2(__hadd2(xb, ya)), v, s10);          \
        s11 = __hfma2(tanh2(__hadd2(xb, yb)), v, s11);          \
    }
            STEP(x) STEP(y) STEP(z) STEP(w)
#undef STEP
        }
        a00 += h2sum(s00);
        a01 += h2sum(s01);
        a10 += h2sum(s10);
        a11 += h2sum(s11);
    }
    float* sc = g_sc + (b * TGT + t0) * SRC + s0;
    sc[ty * SRC + tx] = a00;
    sc[ty * SRC + tx + 16] = a01;
    sc[(ty + 16) * SRC + tx] = a10;
    sc[(ty + 16) * SRC + tx + 16] = a11;
}

// ---------------------------------------------------------------------------
// masked log_softmax over s + transpose to out[b,s,t], coalesced stores.
// grid (8 t-tiles, 8 b), block 256. 32 t-rows per block staged in smem.
// ---------------------------------------------------------------------------
__global__ __launch_bounds__(256) void softmax_kernel(const int* __restrict__ lens,
                                                      float* __restrict__ out) {
    __shared__ float sm[32][257];
    __shared__ float slse[32];
    int tid = threadIdx.x;
    int t0 = blockIdx.x * 32, b = blockIdx.y;
    int len = lens[b];
    const float* scp = g_sc + (b * TGT + t0) * SRC;
#pragma unroll
    for (int i = 0; i < 32; i++) {
        int idx = tid + i * 256;
        int r = idx >> 8, s = idx & 255;
        float v = scp[r * SRC + s];
        if (s >= len) v += LOGEPS;
        sm[r][s] = v;
    }
    __syncthreads();
    int w = tid >> 5, lane = tid & 31;
#pragma unroll
    for (int rr = 0; rr < 4; rr++) {
        int row = w * 4 + rr;
        float m = -1e30f;
        float x[8];
#pragma unroll
        for (int j = 0; j < 8; j++) {
            x[j] = sm[row][lane + 32 * j];
            m = fmaxf(m, x[j]);
        }
#pragma unroll
        for (int o = 16; o; o >>= 1) m = fmaxf(m, __shfl_xor_sync(0xffffffffu, m, o));
        float sum = 0.f;
#pragma unroll
        for (int j = 0; j < 8; j++) sum += __expf(x[j] - m);
#pragma unroll
        for (int o = 16; o; o >>= 1) sum += __shfl_xor_sync(0xffffffffu, sum, o);
        if (lane == 0) slse[row] = m + logf(sum);
    }
    __syncthreads();
    float* op = out + b * SRC * TGT;  // out[b][s][t]
#pragma unroll
    for (int i = 0; i < 32; i++) {
        int idx = tid + i * 256;
        int t = idx & 31, s = idx >> 5;
        op[s * TGT + t0 + t] = sm[t][s] - slse[t];
    }
}

extern "C" void kernel_launch(void* const* d_in, const int* in_sizes, int n_in,
                              void* d_out, int out_size) {
    const float* dec  = (const float*)d_in[0];
    const float* enc  = (const float*)d_in[1];
    const int*   lens = (const int*)d_in[2];
    const float* W1   = (const float*)d_in[3];
    const float* W2   = (const float*)d_in[4];
    const float* vt   = (const float*)d_in[5];
    float*       out  = (float*)d_out;

    gemm_kernel<<<dim3(32, 4, 2), 128>>>(dec, enc, W1, W2);
    scores_kernel<<<dim3(8, 8, 8), 256>>>(vt);
    softmax_kernel<<<dim3(8, 8), 256>>>(lens, out);
}

// round 4
// speedup vs baseline: 1.7457x; 1.0765x over previous
#include <cuda_runtime.h>
#include <cuda_fp16.h>

#define B_   8
#define TGT  256
#define SRC  256
#define DM   512
#define PITCH 132           // half2 words per smem row (128 + 4 pad)
#define LOGEPS (-18.420680743952367f)

#define APITCH 40   // halves; 80B rows -> conflict-free ldmatrix
#define BPITCH 72   // halves; 144B rows -> conflict-free ldmatrix.trans
#define STAGES 4
#define STAGE_HALVES (64 * APITCH + 32 * BPITCH)  // 4864
#define NITER (DM / 32)                            // 16

// scratch (no allocation allowed -> __device__ globals)
__device__ unsigned g_h16[2359296 / 2];          // fp16 copies: dec|enc|W1|W2 (half2 words)
__device__ unsigned g_dt[B_ * TGT * (SRC / 2)];  // dec @ W1  [B,T,L] as half2
__device__ unsigned g_et[B_ * SRC * (SRC / 2)];  // enc @ W2  [B,S,L] as half2
__device__ float    g_sc[B_ * TGT * SRC];        // scores    [B,T,S] fp32

__device__ __forceinline__ __half2 tanh2(__half2 x) {
    unsigned xi = *(unsigned*)&x, yi;
    asm("tanh.approx.f16x2 %0, %1;" : "=r"(yi) : "r"(xi));
    return *(__half2*)&yi;
}
__device__ __forceinline__ __half2 uh(unsigned u) { return *(__half2*)&u; }
__device__ __forceinline__ float h2sum(__half2 h) {
    float2 f = __half22float2(h);
    return f.x + f.y;
}
__device__ __forceinline__ void ldsm4(unsigned& r0, unsigned& r1, unsigned& r2,
                                      unsigned& r3, unsigned addr) {
    asm volatile("ldmatrix.sync.aligned.m8n8.x4.shared.b16 {%0,%1,%2,%3}, [%4];"
                 : "=r"(r0), "=r"(r1), "=r"(r2), "=r"(r3) : "r"(addr));
}
__device__ __forceinline__ void ldsm4t(unsigned& r0, unsigned& r1, unsigned& r2,
                                       unsigned& r3, unsigned addr) {
    asm volatile("ldmatrix.sync.aligned.m8n8.x4.trans.shared.b16 {%0,%1,%2,%3}, [%4];"
                 : "=r"(r0), "=r"(r1), "=r"(r2), "=r"(r3) : "r"(addr));
}
__device__ __forceinline__ void mma16816(float* c, const unsigned* a, unsigned b0,
                                         unsigned b1) {
    asm volatile(
        "mma.sync.aligned.m16n8k16.row.col.f32.f16.f16.f32 "
        "{%0,%1,%2,%3}, {%4,%5,%6,%7}, {%8,%9}, {%0,%1,%2,%3};"
        : "+f"(c[0]), "+f"(c[1]), "+f"(c[2]), "+f"(c[3])
        : "r"(a[0]), "r"(a[1]), "r"(a[2]), "r"(a[3]), "r"(b0), "r"(b1));
}
__device__ __forceinline__ void cpa16(unsigned dst, const void* src) {
    asm volatile("cp.async.ca.shared.global [%0], [%1], 16;" :: "r"(dst), "l"(src));
}

// ---------------------------------------------------------------------------
// fp32 -> fp16 convert: [dec | enc | W1 | W2] into g_h16.
// 589824 float4s, one per thread.
// ---------------------------------------------------------------------------
__global__ __launch_bounds__(256) void convert_kernel(const float* __restrict__ dec,
                                                      const float* __restrict__ enc,
                                                      const float* __restrict__ W1,
                                                      const float* __restrict__ W2) {
    int idx = blockIdx.x * 256 + threadIdx.x;  // float4 index
    const float* src;
    int off;
    if (idx < 262144)      { src = dec; off = idx; }
    else if (idx < 524288) { src = enc; off = idx - 262144; }
    else if (idx < 557056) { src = W1;  off = idx - 524288; }
    else                   { src = W2;  off = idx - 557056; }
    float4 v = ((const float4*)src)[off];
    __half2 h0 = __floats2half2_rn(v.x, v.y);
    __half2 h1 = __floats2half2_rn(v.z, v.w);
    ((uint2*)g_h16)[idx] = make_uint2(*(unsigned*)&h0, *(unsigned*)&h1);
}

// ---------------------------------------------------------------------------
// Tensor-core GEMM, cp.async 4-stage pipeline.
// z=0: g_dt = dec@W1 ; z=1: g_et = enc@W2. fp16 in / fp32 accum / fp16 out.
// Block: 256 threads (8 warps, 2x4), tile 64x64, BK=32.
// ---------------------------------------------------------------------------
__global__ __launch_bounds__(256) void gemm_kernel() {
    __shared__ __half sm_h[STAGES * STAGE_HALVES];
    int z = blockIdx.z;
    const __half* Ag = (const __half*)g_h16 + (z ? 1048576 : 0);
    const __half* Wg = (const __half*)g_h16 + 2097152 + z * 131072;
    unsigned* C = z ? g_et : g_dt;
    int tid = threadIdx.x;
    int warp = tid >> 5, lane = tid & 31;
    int warp_m = warp >> 2, warp_n = warp & 3;
    int bm = blockIdx.x * 64, bn = blockIdx.y * 64;

    unsigned smem_u32 = (unsigned)__cvta_generic_to_shared(sm_h);
    // per-thread cp.async coords
    int ar = tid >> 2, ac = (tid & 3) * 8;     // A: 64 rows x 4 chunks
    int bkr = tid >> 3, bc = (tid & 7) * 8;    // B: 32 rows x 8 chunks
    const __half* srcA0 = Ag + (bm + ar) * DM + ac;
    const __half* srcB0 = Wg + bkr * SRC + bn + bc;
    unsigned dstA0 = smem_u32 + (ar * APITCH + ac) * 2;
    unsigned dstB0 = smem_u32 + (64 * APITCH + bkr * BPITCH + bc) * 2;

#define STAGE_LOAD(st, k0)                                       \
    {                                                            \
        unsigned so = (unsigned)(st) * (STAGE_HALVES * 2);       \
        cpa16(dstA0 + so, srcA0 + (k0));                         \
        cpa16(dstB0 + so, srcB0 + (k0) * SRC);                   \
    }

#pragma unroll
    for (int s = 0; s < STAGES - 1; s++) {
        STAGE_LOAD(s, s * 32);
        asm volatile("cp.async.commit_group;");
    }

    // ldmatrix per-lane bases
    int lm_r = lane & 15, lm_c = (lane >> 4) * 8;
    unsigned a_lm = smem_u32 + ((warp_m * 32 + lm_r) * APITCH + lm_c) * 2;
    unsigned b_lm = smem_u32 + (64 * APITCH + lm_r * BPITCH + warp_n * 16 + lm_c) * 2;

    float acc[2][2][4] = {};
    for (int it = 0; it < NITER; it++) {
        asm volatile("cp.async.wait_group %0;" :: "n"(STAGES - 2));
        __syncthreads();
        int nxt = it + STAGES - 1;
        if (nxt < NITER) STAGE_LOAD(nxt % STAGES, nxt * 32);
        asm volatile("cp.async.commit_group;");

        unsigned so = (unsigned)(it % STAGES) * (STAGE_HALVES * 2);
#pragma unroll
        for (int ks = 0; ks < 2; ks++) {
            unsigned a0[4], a1[4], b[4];
            ldsm4(a0[0], a0[1], a0[2], a0[3], a_lm + so + ks * 32);
            ldsm4(a1[0], a1[1], a1[2], a1[3], a_lm + so + ks * 32 + 16 * APITCH * 2);
            ldsm4t(b[0], b[1], b[2], b[3], b_lm + so + ks * 16 * BPITCH * 2);
            mma16816(acc[0][0], a0, b[0], b[1]);
            mma16816(acc[0][1], a0, b[2], b[3]);
            mma16816(acc[1][0], a1, b[0], b[1]);
            mma16816(acc[1][1], a1, b[2], b[3]);
        }
    }
    // epilogue: fp32 -> half2 stores
#pragma unroll
    for (int rt = 0; rt < 2; rt++) {
        int r0 = bm + warp_m * 32 + rt * 16 + (lane >> 2);
#pragma unroll
        for (int ct = 0; ct < 2; ct++) {
            int colpair = (bn + warp_n * 16 + ct * 8) / 2 + (lane & 3);
            __half2 h01 = __floats2half2_rn(acc[rt][ct][0], acc[rt][ct][1]);
            __half2 h23 = __floats2half2_rn(acc[rt][ct][2], acc[rt][ct][3]);
            C[r0 * (SRC / 2) + colpair] = *(unsigned*)&h01;
            C[(r0 + 8) * (SRC / 2) + colpair] = *(unsigned*)&h23;
        }
    }
#undef STAGE_LOAD
}

// ---------------------------------------------------------------------------
// scores[b,t,s] = sum_l vt[l] * tanh(dt[b,t,l] + et[b,s,l]), f16x2 math,
// HFMA2 accumulate with fp32 flush every 64 l. 32x32 tile, 2x2 micro-tile.
// ---------------------------------------------------------------------------
__global__ __launch_bounds__(256) void scores_kernel(const float* __restrict__ vt) {
    __shared__ unsigned sdt[32 * PITCH];
    __shared__ unsigned set[32 * PITCH];
    __shared__ unsigned svt[128];
    int tid = threadIdx.x;
    int b = blockIdx.z, t0 = blockIdx.y * 32, s0 = blockIdx.x * 32;
    const unsigned* dtp = g_dt + (b * TGT + t0) * (SRC / 2);
    const unsigned* etp = g_et + (b * SRC + s0) * (SRC / 2);
#pragma unroll
    for (int i = 0; i < 4; i++) {
        int idx = tid + i * 256;  // 1024 uint4 per tile
        int r = idx >> 5, q = (idx & 31) * 4;
        *(uint4*)&sdt[r * PITCH + q] = *(const uint4*)&dtp[r * (SRC / 2) + q];
        *(uint4*)&set[r * PITCH + q] = *(const uint4*)&etp[r * (SRC / 2) + q];
    }
    if (tid < 128) {
        __half2 h = __floats2half2_rn(vt[2 * tid], vt[2 * tid + 1]);
        svt[tid] = *(unsigned*)&h;
    }
    __syncthreads();

    int tx = tid & 15, ty = tid >> 4;
    const uint4* pv = (const uint4*)svt;
    const uint4* dA = (const uint4*)(sdt + ty * PITCH);
    const uint4* dB = (const uint4*)(sdt + (ty + 16) * PITCH);
    const uint4* eA = (const uint4*)(set + tx * PITCH);
    const uint4* eB = (const uint4*)(set + (tx + 16) * PITCH);
    float a00 = 0.f, a01 = 0.f, a10 = 0.f, a11 = 0.f;
    for (int p = 0; p < 4; p++) {  // 4 phases x 8 chunks x 4 half2 = 256 l
        __half2 s00 = __float2half2_rn(0.f), s01 = s00, s10 = s00, s11 = s00;
#pragma unroll
        for (int c = p * 8; c < p * 8 + 8; c++) {
            uint4 vv = pv[c];
            uint4 x0 = dA[c], x1 = dB[c];
            uint4 y0 = eA[c], y1 = eB[c];
#define STEP(U)                                                 \
    {                                                           \
        __half2 v = uh(vv.U);                                   \
        __half2 xa = uh(x0.U), xb = uh(x1.U);                   \
        __half2 ya = uh(y0.U), yb = uh(y1.U);                   \
        s00 = __hfma2(tanh2(__hadd2(xa, ya)), v, s00);          \
        s01 = __hfma2(tanh2(__hadd2(xa, yb)), v, s01);          \
        s10 = __hfma2(tanh2(__hadd2(xb, ya)), v, s10);          \
        s11 = __hfma2(tanh2(__hadd2(xb, yb)), v, s11);          \
    }
            STEP(x) STEP(y) STEP(z) STEP(w)
#undef STEP
        }
        a00 += h2sum(s00);
        a01 += h2sum(s01);
        a10 += h2sum(s10);
        a11 += h2sum(s11);
    }
    float* sc = g_sc + (b * TGT + t0) * SRC + s0;
    sc[ty * SRC + tx] = a00;
    sc[ty * SRC + tx + 16] = a01;
    sc[(ty + 16) * SRC + tx] = a10;
    sc[(ty + 16) * SRC + tx + 16] = a11;
}

// ---------------------------------------------------------------------------
// masked log_softmax over s + transpose to out[b,s,t], coalesced stores.
// grid (8 t-tiles, 8 b), block 256. 32 t-rows per block staged in smem.
// ---------------------------------------------------------------------------
__global__ __launch_bounds__(256) void softmax_kernel(const int* __restrict__ lens,
                                                      float* __restrict__ out) {
    __shared__ float sm[32][257];
    __shared__ float slse[32];
    int tid = threadIdx.x;
    int t0 = blockIdx.x * 32, b = blockIdx.y;
    int len = lens[b];
    const float* scp = g_sc + (b * TGT + t0) * SRC;
#pragma unroll
    for (int i = 0; i < 32; i++) {
        int idx = tid + i * 256;
        int r = idx >> 8, s = idx & 255;
        float v = scp[r * SRC + s];
        if (s >= len) v += LOGEPS;
        sm[r][s] = v;
    }
    __syncthreads();
    int w = tid >> 5, lane = tid & 31;
#pragma unroll
    for (int rr = 0; rr < 4; rr++) {
        int row = w * 4 + rr;
        float m = -1e30f;
        float x[8];
#pragma unroll
        for (int j = 0; j < 8; j++) {
            x[j] = sm[row][lane + 32 * j];
            m = fmaxf(m, x[j]);
        }
#pragma unroll
        for (int o = 16; o; o >>= 1) m = fmaxf(m, __shfl_xor_sync(0xffffffffu, m, o));
        float sum = 0.f;
#pragma unroll
        for (int j = 0; j < 8; j++) sum += __expf(x[j] - m);
#pragma unroll
        for (int o = 16; o; o >>= 1) sum += __shfl_xor_sync(0xffffffffu, sum, o);
        if (lane == 0) slse[row] = m + logf(sum);
    }
    __syncthreads();
    float* op = out + b * SRC * TGT;  // out[b][s][t]
#pragma unroll
    for (int i = 0; i < 32; i++) {
        int idx = tid + i * 256;
        int t = idx & 31, s = idx >> 5;
        op[s * TGT + t0 + t] = sm[t][s] - slse[t];
    }
}

extern "C" void kernel_launch(void* const* d_in, const int* in_sizes, int n_in,
                              void* d_out, int out_size) {
    const float* dec  = (const float*)d_in[0];
    const float* enc  = (const float*)d_in[1];
    const int*   lens = (const int*)d_in[2];
    const float* W1   = (const float*)d_in[3];
    const float* W2   = (const float*)d_in[4];
    const float* vt   = (const float*)d_in[5];
    float*       out  = (float*)d_out;

    convert_kernel<<<2304, 256>>>(dec, enc, W1, W2);
    gemm_kernel<<<dim3(32, 4, 2), 256>>>();
    scores_kernel<<<dim3(8, 8, 8), 256>>>(vt);
    softmax_kernel<<<dim3(8, 8), 256>>>(lens, out);
}

// round 5
// speedup vs baseline: 1.8734x; 1.0732x over previous
#include <cuda_runtime.h>
#include <cuda_fp16.h>

#define B_   8
#define TGT  256
#define SRC  256
#define DM   512
#define PITCH 132           // half2 words per smem row (128 + 4 pad)
#define LOGEPS (-18.420680743952367f)

#define APITCH 40    // halves; 80B rows -> conflict-free ldmatrix
#define BPITCH 136   // halves; 272B rows -> conflict-free ldmatrix.trans (128+8)
#define STAGES 4
#define STAGE_HALVES (64 * APITCH + 32 * BPITCH)  // 2560 + 4352 = 6912
#define NITER (DM / 32)                            // 16

// scratch (no allocation allowed -> __device__ globals)
__device__ unsigned g_h16[2359296 / 2];          // fp16 copies: dec|enc|W1|W2 (half2 words)
__device__ unsigned g_dt[B_ * TGT * (SRC / 2)];  // dec @ W1  [B,T,L] as half2
__device__ unsigned g_et[B_ * SRC * (SRC / 2)];  // enc @ W2  [B,S,L] as half2
__device__ float    g_sc[B_ * TGT * SRC];        // scores    [B,T,S] fp32

__device__ __forceinline__ __half2 tanh2(__half2 x) {
    unsigned xi = *(unsigned*)&x, yi;
    asm("tanh.approx.f16x2 %0, %1;" : "=r"(yi) : "r"(xi));
    return *(__half2*)&yi;
}
__device__ __forceinline__ __half2 uh(unsigned u) { return *(__half2*)&u; }
__device__ __forceinline__ float h2sum(__half2 h) {
    float2 f = __half22float2(h);
    return f.x + f.y;
}
__device__ __forceinline__ void ldsm4(unsigned& r0, unsigned& r1, unsigned& r2,
                                      unsigned& r3, unsigned addr) {
    asm volatile("ldmatrix.sync.aligned.m8n8.x4.shared.b16 {%0,%1,%2,%3}, [%4];"
                 : "=r"(r0), "=r"(r1), "=r"(r2), "=r"(r3) : "r"(addr));
}
__device__ __forceinline__ void ldsm4t(unsigned& r0, unsigned& r1, unsigned& r2,
                                       unsigned& r3, unsigned addr) {
    asm volatile("ldmatrix.sync.aligned.m8n8.x4.trans.shared.b16 {%0,%1,%2,%3}, [%4];"
                 : "=r"(r0), "=r"(r1), "=r"(r2), "=r"(r3) : "r"(addr));
}
__device__ __forceinline__ void mma16816(float* c, const unsigned* a, unsigned b0,
                                         unsigned b1) {
    asm volatile(
        "mma.sync.aligned.m16n8k16.row.col.f32.f16.f16.f32 "
        "{%0,%1,%2,%3}, {%4,%5,%6,%7}, {%8,%9}, {%0,%1,%2,%3};"
        : "+f"(c[0]), "+f"(c[1]), "+f"(c[2]), "+f"(c[3])
        : "r"(a[0]), "r"(a[1]), "r"(a[2]), "r"(a[3]), "r"(b0), "r"(b1));
}
__device__ __forceinline__ void cpa16(unsigned dst, const void* src) {
    asm volatile("cp.async.ca.shared.global [%0], [%1], 16;" :: "r"(dst), "l"(src));
}

// ---------------------------------------------------------------------------
// fp32 -> fp16 convert: [dec | enc | W1 | W2] into g_h16. One float4/thread.
// ---------------------------------------------------------------------------
__global__ __launch_bounds__(256) void convert_kernel(const float* __restrict__ dec,
                                                      const float* __restrict__ enc,
                                                      const float* __restrict__ W1,
                                                      const float* __restrict__ W2) {
    int idx = blockIdx.x * 256 + threadIdx.x;  // float4 index
    const float* src;
    int off;
    if (idx < 262144)      { src = dec; off = idx; }
    else if (idx < 524288) { src = enc; off = idx - 262144; }
    else if (idx < 557056) { src = W1;  off = idx - 524288; }
    else                   { src = W2;  off = idx - 557056; }
    float4 v = ((const float4*)src)[off];
    __half2 h0 = __floats2half2_rn(v.x, v.y);
    __half2 h1 = __floats2half2_rn(v.z, v.w);
    ((uint2*)g_h16)[idx] = make_uint2(*(unsigned*)&h0, *(unsigned*)&h1);
}

// ---------------------------------------------------------------------------
// Tensor-core GEMM, cp.async 4-stage pipeline, BM=64 BN=128 BK=32.
// z=0: g_dt = dec@W1 ; z=1: g_et = enc@W2. Grid (32,2,2)=128 CTAs (one wave).
// 256 threads = 8 warps (2 m x 4 n); warp tile 32x32.
// ---------------------------------------------------------------------------
__global__ __launch_bounds__(256) void gemm_kernel() {
    extern __shared__ __half sm_h[];
    int z = blockIdx.z;
    const __half* Ag = (const __half*)g_h16 + (z ? 1048576 : 0);
    const __half* Wg = (const __half*)g_h16 + 2097152 + z * 131072;
    unsigned* C = z ? g_et : g_dt;
    int tid = threadIdx.x;
    int warp = tid >> 5, lane = tid & 31;
    int warp_m = warp >> 2, warp_n = warp & 3;
    int bm = blockIdx.x * 64, bn = blockIdx.y * 128;

    unsigned smem_u32 = (unsigned)__cvta_generic_to_shared(sm_h);
    // per-thread cp.async coords
    int ar = tid >> 2, ac = (tid & 3) * 8;  // A: 64 rows x 4 chunks of 8 halves
    const __half* srcA0 = Ag + (bm + ar) * DM + ac;
    unsigned dstA0 = smem_u32 + (ar * APITCH + ac) * 2;
    // B: 32 rows x 16 chunks = 512 ops, 2 per thread
    int bo0 = tid, bo1 = tid + 256;
    int bkr0 = bo0 >> 4, bc0 = (bo0 & 15) * 8;
    int bkr1 = bo1 >> 4, bc1 = (bo1 & 15) * 8;
    const __half* srcB0 = Wg + bkr0 * SRC + bn + bc0;
    const __half* srcB1 = Wg + bkr1 * SRC + bn + bc1;
    unsigned dstB0 = smem_u32 + (64 * APITCH + bkr0 * BPITCH + bc0) * 2;
    unsigned dstB1 = smem_u32 + (64 * APITCH + bkr1 * BPITCH + bc1) * 2;

#define STAGE_LOAD(st, k0)                                 \
    {                                                      \
        unsigned so = (unsigned)(st) * (STAGE_HALVES * 2); \
        cpa16(dstA0 + so, srcA0 + (k0));                   \
        cpa16(dstB0 + so, srcB0 + (k0) * SRC);             \
        cpa16(dstB1 + so, srcB1 + (k0) * SRC);             \
    }

#pragma unroll
    for (int s = 0; s < STAGES - 1; s++) {
        STAGE_LOAD(s, s * 32);
        asm volatile("cp.async.commit_group;");
    }

    // ldmatrix per-lane bases
    int lm_r = lane & 15, lm_c = (lane >> 4) * 8;
    unsigned a_lm = smem_u32 + ((warp_m * 32 + lm_r) * APITCH + lm_c) * 2;
    unsigned b_lm = smem_u32 + (64 * APITCH + lm_r * BPITCH + warp_n * 32 + lm_c) * 2;

    float acc[2][4][4] = {};
    for (int it = 0; it < NITER; it++) {
        asm volatile("cp.async.wait_group %0;" :: "n"(STAGES - 2));
        __syncthreads();
        int nxt = it + STAGES - 1;
        if (nxt < NITER) STAGE_LOAD(nxt % STAGES, nxt * 32);
        asm volatile("cp.async.commit_group;");

        unsigned so = (unsigned)(it % STAGES) * (STAGE_HALVES * 2);
#pragma unroll
        for (int ks = 0; ks < 2; ks++) {
            unsigned a0[4], a1[4], b0[4], b1[4];
            ldsm4(a0[0], a0[1], a0[2], a0[3], a_lm + so + ks * 32);
            ldsm4(a1[0], a1[1], a1[2], a1[3], a_lm + so + ks * 32 + 16 * APITCH * 2);
            ldsm4t(b0[0], b0[1], b0[2], b0[3], b_lm + so + ks * 16 * BPITCH * 2);
            ldsm4t(b1[0], b1[1], b1[2], b1[3], b_lm + so + ks * 16 * BPITCH * 2 + 32);
            mma16816(acc[0][0], a0, b0[0], b0[1]);
            mma16816(acc[0][1], a0, b0[2], b0[3]);
            mma16816(acc[0][2], a0, b1[0], b1[1]);
            mma16816(acc[0][3], a0, b1[2], b1[3]);
            mma16816(acc[1][0], a1, b0[0], b0[1]);
            mma16816(acc[1][1], a1, b0[2], b0[3]);
            mma16816(acc[1][2], a1, b1[0], b1[1]);
            mma16816(acc[1][3], a1, b1[2], b1[3]);
        }
    }
    // epilogue: fp32 -> half2 stores
#pragma unroll
    for (int rt = 0; rt < 2; rt++) {
        int r0 = bm + warp_m * 32 + rt * 16 + (lane >> 2);
#pragma unroll
        for (int ct = 0; ct < 4; ct++) {
            int colpair = (bn + warp_n * 32 + ct * 8) / 2 + (lane & 3);
            __half2 h01 = __floats2half2_rn(acc[rt][ct][0], acc[rt][ct][1]);
            __half2 h23 = __floats2half2_rn(acc[rt][ct][2], acc[rt][ct][3]);
            C[r0 * (SRC / 2) + colpair] = *(unsigned*)&h01;
            C[(r0 + 8) * (SRC / 2) + colpair] = *(unsigned*)&h23;
        }
    }
#undef STAGE_LOAD
}

// ---------------------------------------------------------------------------
// scores[b,t,s] = sum_l vt[l] * tanh(dt[b,t,l] + et[b,s,l]), f16x2 math,
// HFMA2 accumulate with fp32 flush every 64 l. 32x32 tile, 2x2 micro-tile.
// ---------------------------------------------------------------------------
__global__ __launch_bounds__(256) void scores_kernel(const float* __restrict__ vt) {
    __shared__ unsigned sdt[32 * PITCH];
    __shared__ unsigned set[32 * PITCH];
    __shared__ unsigned svt[128];
    int tid = threadIdx.x;
    int b = blockIdx.z, t0 = blockIdx.y * 32, s0 = blockIdx.x * 32;
    const unsigned* dtp = g_dt + (b * TGT + t0) * (SRC / 2);
    const unsigned* etp = g_et + (b * SRC + s0) * (SRC / 2);
#pragma unroll
    for (int i = 0; i < 4; i++) {
        int idx = tid + i * 256;  // 1024 uint4 per tile
        int r = idx >> 5, q = (idx & 31) * 4;
        *(uint4*)&sdt[r * PITCH + q] = *(const uint4*)&dtp[r * (SRC / 2) + q];
        *(uint4*)&set[r * PITCH + q] = *(const uint4*)&etp[r * (SRC / 2) + q];
    }
    if (tid < 128) {
        __half2 h = __floats2half2_rn(vt[2 * tid], vt[2 * tid + 1]);
        svt[tid] = *(unsigned*)&h;
    }
    __syncthreads();

    int tx = tid & 15, ty = tid >> 4;
    const uint4* pv = (const uint4*)svt;
    const uint4* dA = (const uint4*)(sdt + ty * PITCH);
    const uint4* dB = (const uint4*)(sdt + (ty + 16) * PITCH);
    const uint4* eA = (const uint4*)(set + tx * PITCH);
    const uint4* eB = (const uint4*)(set + (tx + 16) * PITCH);
    float a00 = 0.f, a01 = 0.f, a10 = 0.f, a11 = 0.f;
    for (int p = 0; p < 4; p++) {  // 4 phases x 8 chunks x 4 half2 = 256 l
        __half2 s00 = __float2half2_rn(0.f), s01 = s00, s10 = s00, s11 = s00;
#pragma unroll
        for (int c = p * 8; c < p * 8 + 8; c++) {
            uint4 vv = pv[c];
            uint4 x0 = dA[c], x1 = dB[c];
            uint4 y0 = eA[c], y1 = eB[c];
#define STEP(U)                                                 \
    {                                                           \
        __half2 v = uh(vv.U);                                   \
        __half2 xa = uh(x0.U), xb = uh(x1.U);                   \
        __half2 ya = uh(y0.U), yb = uh(y1.U);                   \
        s00 = __hfma2(tanh2(__hadd2(xa, ya)), v, s00);          \
        s01 = __hfma2(tanh2(__hadd2(xa, yb)), v, s01);          \
        s10 = __hfma2(tanh2(__hadd2(xb, ya)), v, s10);          \
        s11 = __hfma2(tanh2(__hadd2(xb, yb)), v, s11);          \
    }
            STEP(x) STEP(y) STEP(z) STEP(w)
#undef STEP
        }
        a00 += h2sum(s00);
        a01 += h2sum(s01);
        a10 += h2sum(s10);
        a11 += h2sum(s11);
    }
    float* sc = g_sc + (b * TGT + t0) * SRC + s0;
    sc[ty * SRC + tx] = a00;
    sc[ty * SRC + tx + 16] = a01;
    sc[(ty + 16) * SRC + tx] = a10;
    sc[(ty + 16) * SRC + tx + 16] = a11;
}

// ---------------------------------------------------------------------------
// masked log_softmax over s + transpose to out[b,s,t].
// grid (32 t-tiles, 8 b) = 256 blocks; 8 t-rows per block, one warp per row.
// ---------------------------------------------------------------------------
__global__ __launch_bounds__(256) void softmax_kernel(const int* __restrict__ lens,
                                                      float* __restrict__ out) {
    __shared__ float sm[8][260];
    __shared__ float slse[8];
    int tid = threadIdx.x;
    int t0 = blockIdx.x * 8, b = blockIdx.y;
    int len = lens[b];
    const float* scp = g_sc + (b * TGT + t0) * SRC;
#pragma unroll
    for (int i = 0; i < 2; i++) {
        int idx = tid + i * 256;  // 512 float4 = 8 rows x 64 chunks
        int r = idx >> 6, s4 = (idx & 63) * 4;
        float4 v = *(const float4*)&scp[r * SRC + s4];
        if (s4 + 3 >= len) {
            if (s4 + 0 >= len) v.x += LOGEPS;
            if (s4 + 1 >= len) v.y += LOGEPS;
            if (s4 + 2 >= len) v.z += LOGEPS;
            if (s4 + 3 >= len) v.w += LOGEPS;
        }
        *(float4*)&sm[r][s4] = v;
    }
    __syncthreads();
    int w = tid >> 5, lane = tid & 31;
    {
        float m = -1e30f;
        float x[8];
#pragma unroll
        for (int j = 0; j < 8; j++) {
            x[j] = sm[w][lane + 32 * j];
            m = fmaxf(m, x[j]);
        }
#pragma unroll
        for (int o = 16; o; o >>= 1) m = fmaxf(m, __shfl_xor_sync(0xffffffffu, m, o));
        float sum = 0.f;
#pragma unroll
        for (int j = 0; j < 8; j++) sum += __expf(x[j] - m);
#pragma unroll
        for (int o = 16; o; o >>= 1) sum += __shfl_xor_sync(0xffffffffu, sum, o);
        if (lane == 0) slse[w] = m + logf(sum);
    }
    __syncthreads();
    float* op = out + b * SRC * TGT;  // out[b][s][t]
#pragma unroll
    for (int i = 0; i < 8; i++) {
        int idx = tid + i * 256;
        int t = idx & 7, s = idx >> 3;
        op[s * TGT + t0 + t] = sm[t][s] - slse[t];
    }
}

extern "C" void kernel_launch(void* const* d_in, const int* in_sizes, int n_in,
                              void* d_out, int out_size) {
    const float* dec  = (const float*)d_in[0];
    const float* enc  = (const float*)d_in[1];
    const int*   lens = (const int*)d_in[2];
    const float* W1   = (const float*)d_in[3];
    const float* W2   = (const float*)d_in[4];
    const float* vt   = (const float*)d_in[5];
    float*       out  = (float*)d_out;

    convert_kernel<<<2304, 256>>>(dec, enc, W1, W2);

    constexpr int GEMM_SMEM = STAGES * STAGE_HALVES * 2;  // 55296 B
    cudaFuncSetAttribute(gemm_kernel, cudaFuncAttributeMaxDynamicSharedMemorySize,
                         GEMM_SMEM);
    gemm_kernel<<<dim3(32, 2, 2), 256, GEMM_SMEM>>>();

    scores_kernel<<<dim3(8, 8, 8), 256>>>(vt);
    softmax_kernel<<<dim3(32, 8), 256>>>(lens, out);
}